// round 5
// baseline (speedup 1.0000x reference)
#include <cuda_runtime.h>

// ---------------- problem dims (compile-time) ----------------
#define L_SEQ   1024
#define D_MODEL 512
#define N_B     2
#define N_H     8
#define N_P     4
#define INV_TEMP 0.125f     // 1/sqrt(64)
#define LN_EPS   1e-6f

#define OUT_ELEMS  (N_P * N_B * L_SEQ * D_MODEL)     // 4,194,304
#define ATTN_ELEMS (N_B * N_H * L_SEQ * L_SEQ)       // 16,777,216

// ---------------- device scratch (no allocations allowed) ----------------
__device__ float g_qn[N_B * L_SEQ * D_MODEL];
__device__ float g_qh[N_B * L_SEQ * D_MODEL];
__device__ float g_kh[N_B * L_SEQ * D_MODEL];
__device__ float g_vh[N_B * L_SEQ * D_MODEL];
__device__ float g_ho[N_P * N_B * L_SEQ * D_MODEL];
__device__ float g_attn_fallback[ATTN_ELEMS];        // used only if d_out lacks room for attn

// ---------------- packed f32x2 helpers (sm_103a FFMA2 path) ----------------
__device__ __forceinline__ unsigned long long pk2(float x, float y) {
    unsigned long long r;
    asm("mov.b64 %0, {%1, %2};" : "=l"(r) : "f"(x), "f"(y));
    return r;
}
__device__ __forceinline__ void fma2(unsigned long long& c, unsigned long long a, unsigned long long b) {
    asm("fma.rn.f32x2 %0, %1, %2, %0;" : "+l"(c) : "l"(a), "l"(b));
}
__device__ __forceinline__ float2 upk2(unsigned long long v) {
    float2 r;
    asm("mov.b64 {%0, %1}, %2;" : "=f"(r.x), "=f"(r.y) : "l"(v));
    return r;
}

// ---------------- LayerNorm over last dim (512) ----------------
// one block per row, 128 threads, 4 floats (one float4) per thread
__global__ __launch_bounds__(128)
void ln_kernel(const float* __restrict__ q, const float* __restrict__ g,
               const float* __restrict__ b, float* __restrict__ out) {
    int row = blockIdx.x;
    const float* x = q + (size_t)row * D_MODEL;
    int tid = threadIdx.x;
    float4 v = reinterpret_cast<const float4*>(x)[tid];
    float s  = v.x + v.y + v.z + v.w;
    float s2 = v.x * v.x + v.y * v.y + v.z * v.z + v.w * v.w;
    #pragma unroll
    for (int o = 16; o > 0; o >>= 1) {
        s  += __shfl_xor_sync(0xffffffffu, s,  o);
        s2 += __shfl_xor_sync(0xffffffffu, s2, o);
    }
    __shared__ float shs[4], shs2[4];
    __shared__ float sh_mu, sh_rs;
    int w = tid >> 5;
    if ((tid & 31) == 0) { shs[w] = s; shs2[w] = s2; }
    __syncthreads();
    if (tid == 0) {
        float S  = shs[0] + shs[1] + shs[2] + shs[3];
        float S2 = shs2[0] + shs2[1] + shs2[2] + shs2[3];
        float mu = S * (1.0f / D_MODEL);
        float var = S2 * (1.0f / D_MODEL) - mu * mu;
        sh_mu = mu;
        sh_rs = rsqrtf(var + LN_EPS);
    }
    __syncthreads();
    float mu = sh_mu, rs = sh_rs;
    float4 gv = reinterpret_cast<const float4*>(g)[tid];
    float4 bv = reinterpret_cast<const float4*>(b)[tid];
    float4 o;
    o.x = (v.x - mu) * rs * gv.x + bv.x;
    o.y = (v.y - mu) * rs * gv.y + bv.y;
    o.z = (v.z - mu) * rs * gv.z + bv.z;
    o.w = (v.w - mu) * rs * gv.w + bv.w;
    reinterpret_cast<float4*>(out + (size_t)row * D_MODEL)[tid] = o;
}

// ---------------- generic 64x64-tile SGEMM: C[m,n] = sum_k A[m,k]*W[n,k] ----------------
// modes: 0 = scale by INV_TEMP (q proj), 1 = plain (k/v proj),
//        2 = batched attention scores (z = b*8+h), 3 = FC (+bias +residual)
#define GM_SCALE 0
#define GM_PLAIN 1
#define GM_ATTN  2
#define GM_FC    3

template <int MODE>
__global__ __launch_bounds__(256)
void gemm64(const float* __restrict__ A, const float* __restrict__ W,
            float* __restrict__ C, int K, int lda, int ldb, int ldc,
            const float* __restrict__ bias, const float* __restrict__ resid) {
    __shared__ float As[16][64];   // [k][m]
    __shared__ float Bs[16][64];   // [k][n]

    int tid = threadIdx.x;
    int tx = tid & 15, ty = tid >> 4;
    int lr = tid >> 2;             // 0..63 (tile row for loads)
    int lc = (tid & 3) << 2;       // 0,4,8,12 (k offset for loads)
    int m0 = blockIdx.y << 6, n0 = blockIdx.x << 6;

    const float* Ap = A;
    const float* Wp = W;
    float* Cp = C;
    if (MODE == GM_ATTN) {
        int z = blockIdx.z, b = z >> 3, h = z & 7;
        size_t off = (size_t)b * L_SEQ * D_MODEL + (size_t)h * 64;
        Ap += off;
        Wp += off;
        Cp += (size_t)z * L_SEQ * L_SEQ;
    }
    const float* arow = Ap + (size_t)(m0 + lr) * lda + lc;
    const float* brow = Wp + (size_t)(n0 + lr) * ldb + lc;

    unsigned long long acc[4][2];
    #pragma unroll
    for (int i = 0; i < 4; i++) { acc[i][0] = 0ull; acc[i][1] = 0ull; }

    for (int k0 = 0; k0 < K; k0 += 16) {
        float4 av = *reinterpret_cast<const float4*>(arow + k0);
        float4 bv = *reinterpret_cast<const float4*>(brow + k0);
        if (k0) __syncthreads();
        As[lc + 0][lr] = av.x; As[lc + 1][lr] = av.y;
        As[lc + 2][lr] = av.z; As[lc + 3][lr] = av.w;
        Bs[lc + 0][lr] = bv.x; Bs[lc + 1][lr] = bv.y;
        Bs[lc + 2][lr] = bv.z; Bs[lc + 3][lr] = bv.w;
        __syncthreads();
        #pragma unroll
        for (int kk = 0; kk < 16; kk++) {
            float4 a4 = *reinterpret_cast<const float4*>(&As[kk][ty << 2]);
            float4 b4 = *reinterpret_cast<const float4*>(&Bs[kk][tx << 2]);
            unsigned long long b01 = pk2(b4.x, b4.y);
            unsigned long long b23 = pk2(b4.z, b4.w);
            unsigned long long a0 = pk2(a4.x, a4.x);
            unsigned long long a1 = pk2(a4.y, a4.y);
            unsigned long long a2 = pk2(a4.z, a4.z);
            unsigned long long a3 = pk2(a4.w, a4.w);
            fma2(acc[0][0], a0, b01); fma2(acc[0][1], a0, b23);
            fma2(acc[1][0], a1, b01); fma2(acc[1][1], a1, b23);
            fma2(acc[2][0], a2, b01); fma2(acc[2][1], a2, b23);
            fma2(acc[3][0], a3, b01); fma2(acc[3][1], a3, b23);
        }
    }

    #pragma unroll
    for (int i = 0; i < 4; i++) {
        int row = m0 + (ty << 2) + i;
        int col = n0 + (tx << 2);
        float2 c01 = upk2(acc[i][0]);
        float2 c23 = upk2(acc[i][1]);
        float4 r = make_float4(c01.x, c01.y, c23.x, c23.y);
        if (MODE == GM_SCALE) {
            r.x *= INV_TEMP; r.y *= INV_TEMP; r.z *= INV_TEMP; r.w *= INV_TEMP;
        }
        if (MODE == GM_FC) {
            float4 bb = *reinterpret_cast<const float4*>(bias + col);
            const float* rp = resid + (size_t)(row & (N_B * L_SEQ - 1)) * D_MODEL + col;
            float4 rv = *reinterpret_cast<const float4*>(rp);
            r.x += bb.x + rv.x; r.y += bb.y + rv.y;
            r.z += bb.z + rv.z; r.w += bb.w + rv.w;
        }
        *reinterpret_cast<float4*>(Cp + (size_t)row * ldc + col) = r;
    }
}

// ---------------- fused masked softmax + P*V ----------------
// grid: (qtile 16, bh 16, p 4); block 256.
// e = mask * expf(s); no max subtraction needed (|s| <= ~6).
// Accumulates unnormalized O = e*V and row sums Z in one pass; divides at the end.
__global__ __launch_bounds__(256)
void softmax_pv(const float* __restrict__ attn, const float* __restrict__ mask,
                const float* __restrict__ vh, float* __restrict__ ho) {
    __shared__ float Es[64][68];   // [qrow][k], padded
    __shared__ float Vs[64][64];   // [k][d]
    __shared__ float Zs[64];

    int tid = threadIdx.x;
    int tx = tid & 15, ty = tid >> 4;
    int lr = tid >> 2;              // 0..63
    int lc = (tid & 3) << 4;        // 0,16,32,48

    int q0 = blockIdx.x << 6;
    int bh = blockIdx.y, b = bh >> 3, h = bh & 7;
    int p = blockIdx.z;

    const float* Sp = attn + (size_t)bh * L_SEQ * L_SEQ + (size_t)(q0 + lr) * L_SEQ;
    const float* Mp = mask + (size_t)p * L_SEQ * L_SEQ + (size_t)(q0 + lr) * L_SEQ;
    const float* Vp = vh + (size_t)b * L_SEQ * D_MODEL + (size_t)h * 64;

    unsigned long long acc[4][2];
    #pragma unroll
    for (int i = 0; i < 4; i++) { acc[i][0] = 0ull; acc[i][1] = 0ull; }
    float zacc = 0.0f;

    for (int kt = 0; kt < 16; kt++) {
        int kb = kt << 6;
        __syncthreads();   // previous tile's compute finished before overwrite
        float rs = 0.0f;
        #pragma unroll
        for (int j = 0; j < 4; j++) {
            float4 s4 = *reinterpret_cast<const float4*>(Sp + kb + lc + 4 * j);
            float4 m4 = *reinterpret_cast<const float4*>(Mp + kb + lc + 4 * j);
            float4 e;
            e.x = m4.x * __expf(s4.x);
            e.y = m4.y * __expf(s4.y);
            e.z = m4.z * __expf(s4.z);
            e.w = m4.w * __expf(s4.w);
            rs += e.x + e.y + e.z + e.w;
            *reinterpret_cast<float4*>(&Es[lr][lc + 4 * j]) = e;
        }
        rs += __shfl_xor_sync(0xffffffffu, rs, 1);
        rs += __shfl_xor_sync(0xffffffffu, rs, 2);
        if ((tid & 3) == 0) zacc += rs;

        #pragma unroll
        for (int j = 0; j < 4; j++) {
            *reinterpret_cast<float4*>(&Vs[lr][lc + 4 * j]) =
                *reinterpret_cast<const float4*>(Vp + (size_t)(kb + lr) * D_MODEL + lc + 4 * j);
        }
        __syncthreads();

        #pragma unroll 8
        for (int kk = 0; kk < 64; kk++) {
            float a0 = Es[(ty << 2) + 0][kk];
            float a1 = Es[(ty << 2) + 1][kk];
            float a2 = Es[(ty << 2) + 2][kk];
            float a3 = Es[(ty << 2) + 3][kk];
            float4 b4 = *reinterpret_cast<const float4*>(&Vs[kk][tx << 2]);
            unsigned long long b01 = pk2(b4.x, b4.y);
            unsigned long long b23 = pk2(b4.z, b4.w);
            unsigned long long p0 = pk2(a0, a0);
            unsigned long long p1 = pk2(a1, a1);
            unsigned long long p2 = pk2(a2, a2);
            unsigned long long p3 = pk2(a3, a3);
            fma2(acc[0][0], p0, b01); fma2(acc[0][1], p0, b23);
            fma2(acc[1][0], p1, b01); fma2(acc[1][1], p1, b23);
            fma2(acc[2][0], p2, b01); fma2(acc[2][1], p2, b23);
            fma2(acc[3][0], p3, b01); fma2(acc[3][1], p3, b23);
        }
    }

    if ((tid & 3) == 0) Zs[lr] = zacc;
    __syncthreads();

    float* hop = ho + ((size_t)((p * N_B + b) * L_SEQ + q0)) * D_MODEL + (size_t)h * 64;
    #pragma unroll
    for (int i = 0; i < 4; i++) {
        int row = (ty << 2) + i;
        float zi = 1.0f / Zs[row];
        float2 c01 = upk2(acc[i][0]);
        float2 c23 = upk2(acc[i][1]);
        float4 r = make_float4(c01.x * zi, c01.y * zi, c23.x * zi, c23.y * zi);
        *reinterpret_cast<float4*>(hop + (size_t)row * D_MODEL + (tx << 2)) = r;
    }
}

// ---------------- launch ----------------
extern "C" void kernel_launch(void* const* d_in, const int* in_sizes, int n_in,
                              void* d_out, int out_size) {
    const float* q    = (const float*)d_in[0];
    const float* k    = (const float*)d_in[1];
    const float* v    = (const float*)d_in[2];
    const float* mask = (const float*)d_in[3];
    const float* w_q  = (const float*)d_in[4];
    const float* w_k  = (const float*)d_in[5];
    const float* w_v  = (const float*)d_in[6];
    const float* fc_w = (const float*)d_in[7];
    const float* fc_b = (const float*)d_in[8];
    const float* ln_g = (const float*)d_in[9];
    const float* ln_b = (const float*)d_in[10];

    float* out = (float*)d_out;

    float *qn, *qh, *kh, *vh, *ho, *attn_fb;
    cudaGetSymbolAddress((void**)&qn, g_qn);
    cudaGetSymbolAddress((void**)&qh, g_qh);
    cudaGetSymbolAddress((void**)&kh, g_kh);
    cudaGetSymbolAddress((void**)&vh, g_vh);
    cudaGetSymbolAddress((void**)&ho, g_ho);
    cudaGetSymbolAddress((void**)&attn_fb, g_attn_fallback);

    // attn tensor is the second output; write it into d_out if there's room
    float* attn_out = (out_size >= OUT_ELEMS + ATTN_ELEMS) ? out + OUT_ELEMS : attn_fb;

    // 1. pre-LN on q
    ln_kernel<<<N_B * L_SEQ, 128>>>(q, ln_g, ln_b, qn);

    // 2-4. projections (q projection folds in 1/sqrt(dk))
    dim3 gproj(D_MODEL / 64, (N_B * L_SEQ) / 64, 1);          // (8, 32)
    gemm64<GM_SCALE><<<gproj, 256>>>(qn, w_q, qh, D_MODEL, D_MODEL, D_MODEL, D_MODEL, nullptr, nullptr);
    gemm64<GM_PLAIN><<<gproj, 256>>>(k,  w_k, kh, D_MODEL, D_MODEL, D_MODEL, D_MODEL, nullptr, nullptr);
    gemm64<GM_PLAIN><<<gproj, 256>>>(v,  w_v, vh, D_MODEL, D_MODEL, D_MODEL, D_MODEL, nullptr, nullptr);

    // 5. attention scores: per (b,h): S[1024,1024] = qh_bh (1024x64) * kh_bh^T
    dim3 gattn(L_SEQ / 64, L_SEQ / 64, N_B * N_H);            // (16, 16, 16)
    gemm64<GM_ATTN><<<gattn, 256>>>(qh, kh, attn_out, 64, D_MODEL, D_MODEL, L_SEQ, nullptr, nullptr);

    // 6. fused masked softmax + PV for all P masks
    dim3 gsm(L_SEQ / 64, N_B * N_H, N_P);                     // (16, 16, 4)
    softmax_pv<<<gsm, 256>>>(attn_out, mask, vh, ho);

    // 7. FC + bias + residual -> out [P,B,L,D]
    dim3 gfc(D_MODEL / 64, (N_P * N_B * L_SEQ) / 64, 1);      // (8, 128)
    gemm64<GM_FC><<<gfc, 256>>>(ho, fc_w, out, D_MODEL, D_MODEL, D_MODEL, D_MODEL, fc_b, q);
}